// round 16
// baseline (speedup 1.0000x reference)
#include <cuda_runtime.h>
#include <cuda_fp16.h>
#include <cstdint>

#define N_NODES 50000
#define OUT_DIM 128
#define IN_DIM  256
#define CAP     64          // slots per row per relation (Poisson(16) edges/row)

// ---------------------------------------------------------------------------
// Device-global scratch. Referenced only from device code.
// ---------------------------------------------------------------------------
__device__ uint2 g_xw1h[(size_t)N_NODES * 32];
__device__ uint2 g_xw2h[(size_t)N_NODES * 32];
__device__ uint4 g_wih[IN_DIM * 32];   // interleaved fp16 W: .xy=W1 4 halves, .zw=W2

// Bucketed edge store. rel: 0=feat, 1=adj1, 2=adj2.
__device__ int      g_cnt[3 * N_NODES];
__device__ unsigned g_pack[3 * (size_t)N_NODES * CAP];  // {fp16 val | 16-bit col}

// ---------------------------------------------------------------------------
// packed-math helpers (sm_103a: fma.rn.f32x2 -> FFMA2)
// ---------------------------------------------------------------------------
__device__ __forceinline__ unsigned long long pack_ff(float lo, float hi) {
    unsigned long long r;
    asm("mov.b64 %0, {%1, %2};" : "=l"(r) : "f"(lo), "f"(hi));
    return r;
}
__device__ __forceinline__ float2 unpack_ff(unsigned long long r) {
    float2 f;
    asm("mov.b64 {%0, %1}, %2;" : "=f"(f.x), "=f"(f.y) : "l"(r));
    return f;
}
__device__ __forceinline__ void fma2(unsigned long long& acc,
                                     unsigned long long a, unsigned long long b) {
    asm("fma.rn.f32x2 %0, %1, %2, %0;" : "+l"(acc) : "l"(a), "l"(b));
}
// half2 (as unsigned) -> packed 2xf32 in a 64-bit reg
__device__ __forceinline__ unsigned long long h2_to_ff(unsigned h2) {
    float2 f = __half22float2(*reinterpret_cast<__half2*>(&h2));
    return pack_ff(f.x, f.y);
}
__device__ __forceinline__ uint2 f4_to_h4(float4 f) {
    __half2 h01 = __floats2half2_rn(f.x, f.y);
    __half2 h23 = __floats2half2_rn(f.z, f.w);
    uint2 u;
    u.x = *reinterpret_cast<unsigned*>(&h01);
    u.y = *reinterpret_cast<unsigned*>(&h23);
    return u;
}
__device__ __forceinline__ float pack_val(unsigned p) {
    return __half2float(__ushort_as_half((unsigned short)(p >> 16)));
}
__device__ __forceinline__ unsigned make_pack(int c, float v) {
    unsigned hv = (unsigned)__half_as_ushort(__float2half_rn(v));
    return (hv << 16) | (unsigned)c;
}
__device__ __forceinline__ uint2 ff2_to_h4(unsigned long long lo, unsigned long long hi) {
    float2 f01 = unpack_ff(lo);
    float2 f23 = unpack_ff(hi);
    return f4_to_h4(make_float4(f01.x, f01.y, f23.x, f23.y));
}

// ---------------------------------------------------------------------------
// 1) zero counters + build interleaved fp16 W table
// ---------------------------------------------------------------------------
__global__ void prep_kernel(const float* __restrict__ W1,
                            const float* __restrict__ W2) {
    int stride = gridDim.x * blockDim.x;
    int tid = blockIdx.x * blockDim.x + threadIdx.x;
    for (int i = tid; i < 3 * N_NODES; i += stride)
        g_cnt[i] = 0;
    for (int i = tid; i < IN_DIM * 32; i += stride) {
        uint2 h1 = f4_to_h4(reinterpret_cast<const float4*>(W1)[i]);
        uint2 h2 = f4_to_h4(reinterpret_cast<const float4*>(W2)[i]);
        g_wih[i] = make_uint4(h1.x, h1.y, h2.x, h2.y);
    }
}

// ---------------------------------------------------------------------------
// 2) bucket scatter: pos = atomicAdd(cnt[r]); pack[r*CAP+pos] = edge.
// ---------------------------------------------------------------------------
__device__ __forceinline__ void scatter_one(const int* __restrict__ rows,
                                            const int* __restrict__ cols,
                                            const float* __restrict__ vals,
                                            int n, int rel, int tid, int nthreads) {
    int* cnt = g_cnt + rel * N_NODES;
    unsigned* pk = g_pack + (size_t)rel * N_NODES * CAP;
    int n4 = n >> 2;
    const int4*   r4 = reinterpret_cast<const int4*>(rows);
    const int4*   c4 = reinterpret_cast<const int4*>(cols);
    const float4* v4 = reinterpret_cast<const float4*>(vals);
    for (int i = tid; i < n4; i += nthreads) {
        int4   r = r4[i];
        int4   c = c4[i];
        float4 v = v4[i];
        int p0 = atomicAdd(&cnt[r.x], 1);
        int p1 = atomicAdd(&cnt[r.y], 1);
        int p2 = atomicAdd(&cnt[r.z], 1);
        int p3 = atomicAdd(&cnt[r.w], 1);
        if (p0 < CAP) pk[(size_t)r.x * CAP + p0] = make_pack(c.x, v.x);
        if (p1 < CAP) pk[(size_t)r.y * CAP + p1] = make_pack(c.y, v.y);
        if (p2 < CAP) pk[(size_t)r.z * CAP + p2] = make_pack(c.z, v.z);
        if (p3 < CAP) pk[(size_t)r.w * CAP + p3] = make_pack(c.w, v.w);
    }
    for (int i = (n4 << 2) + tid; i < n; i += nthreads) {
        int r = rows[i];
        int pos = atomicAdd(&cnt[r], 1);
        if (pos < CAP) pk[(size_t)r * CAP + pos] = make_pack(cols[i], vals[i]);
    }
}

__global__ void scatter_feat_kernel(const int* __restrict__ frow,
                                    const int* __restrict__ fcol,
                                    const float* __restrict__ fval, int nf) {
    int tid = blockIdx.x * blockDim.x + threadIdx.x;
    scatter_one(frow, fcol, fval, nf, 0, tid, gridDim.x * blockDim.x);
}

__global__ void scatter_adj_kernel(const int* __restrict__ a1row, const int* __restrict__ a1col,
                                   const float* __restrict__ a1val,
                                   const int* __restrict__ a2row, const int* __restrict__ a2col,
                                   const float* __restrict__ a2val,
                                   int n1, int n2) {
    int tid = blockIdx.x * blockDim.x + threadIdx.x;
    int nthreads = gridDim.x * blockDim.x;
    scatter_one(a1row, a1col, a1val, n1, 1, tid, nthreads);
    scatter_one(a2row, a2col, a2val, n2, 2, tid, nthreads);
}

// ---------------------------------------------------------------------------
// 3) feature SpMM: one warp per node, one LDG.128 per (col,lane) fetching
//    both W1 and W2; packed f32x2 FMAs; fp16 stores.
// ---------------------------------------------------------------------------
__global__ void feat_csr_kernel() {
    int r    = (blockIdx.x * blockDim.x + threadIdx.x) >> 5;
    int lane = threadIdx.x & 31;
    if (r >= N_NODES) return;

    int deg = g_cnt[r];
    if (deg > CAP) deg = CAP;
    const unsigned* pk = g_pack + (size_t)r * CAP;

    unsigned long long a1lo = 0ULL, a1hi = 0ULL;   // xw1 cols 01 / 23
    unsigned long long a2lo = 0ULL, a2hi = 0ULL;   // xw2 cols 01 / 23

    int i = 0;
    for (; i + 4 <= deg; i += 4) {
        unsigned p0 = pk[i], p1 = pk[i + 1], p2 = pk[i + 2], p3 = pk[i + 3];
        uint4 w0 = g_wih[(p0 & 0xFFFF) * 32 + lane];
        uint4 w1 = g_wih[(p1 & 0xFFFF) * 32 + lane];
        uint4 w2 = g_wih[(p2 & 0xFFFF) * 32 + lane];
        uint4 w3 = g_wih[(p3 & 0xFFFF) * 32 + lane];
        float f0 = pack_val(p0), f1 = pack_val(p1), f2 = pack_val(p2), f3 = pack_val(p3);
        unsigned long long v0 = pack_ff(f0, f0), v1 = pack_ff(f1, f1);
        unsigned long long v2 = pack_ff(f2, f2), v3 = pack_ff(f3, f3);
        fma2(a1lo, h2_to_ff(w0.x), v0); fma2(a1hi, h2_to_ff(w0.y), v0);
        fma2(a2lo, h2_to_ff(w0.z), v0); fma2(a2hi, h2_to_ff(w0.w), v0);
        fma2(a1lo, h2_to_ff(w1.x), v1); fma2(a1hi, h2_to_ff(w1.y), v1);
        fma2(a2lo, h2_to_ff(w1.z), v1); fma2(a2hi, h2_to_ff(w1.w), v1);
        fma2(a1lo, h2_to_ff(w2.x), v2); fma2(a1hi, h2_to_ff(w2.y), v2);
        fma2(a2lo, h2_to_ff(w2.z), v2); fma2(a2hi, h2_to_ff(w2.w), v2);
        fma2(a1lo, h2_to_ff(w3.x), v3); fma2(a1hi, h2_to_ff(w3.y), v3);
        fma2(a2lo, h2_to_ff(w3.z), v3); fma2(a2hi, h2_to_ff(w3.w), v3);
    }
    for (; i < deg; i++) {
        unsigned p = pk[i];
        uint4 w = g_wih[(p & 0xFFFF) * 32 + lane];
        float f = pack_val(p);
        unsigned long long v = pack_ff(f, f);
        fma2(a1lo, h2_to_ff(w.x), v); fma2(a1hi, h2_to_ff(w.y), v);
        fma2(a2lo, h2_to_ff(w.z), v); fma2(a2hi, h2_to_ff(w.w), v);
    }
    g_xw1h[(size_t)r * 32 + lane] = ff2_to_h4(a1lo, a1hi);
    g_xw2h[(size_t)r * 32 + lane] = ff2_to_h4(a2lo, a2hi);
}

// ---------------------------------------------------------------------------
// 4) adjacency SpMM (both relations) + relu: packed f32x2 FMAs.
// ---------------------------------------------------------------------------
template <int REL>
__device__ __forceinline__ void adj_accum(int r, int lane, const uint2* __restrict__ H,
                                          unsigned long long& aLo,
                                          unsigned long long& aHi,
                                          unsigned long long& bLo,
                                          unsigned long long& bHi) {
    int deg = g_cnt[REL * N_NODES + r];
    if (deg > CAP) deg = CAP;
    const unsigned* pk = g_pack + ((size_t)REL * N_NODES + r) * CAP;

    int i = 0;
    for (; i + 4 <= deg; i += 4) {
        unsigned p0 = pk[i], p1 = pk[i + 1], p2 = pk[i + 2], p3 = pk[i + 3];
        uint2 h0 = H[(size_t)(p0 & 0xFFFF) * 32 + lane];
        uint2 h1 = H[(size_t)(p1 & 0xFFFF) * 32 + lane];
        uint2 h2 = H[(size_t)(p2 & 0xFFFF) * 32 + lane];
        uint2 h3 = H[(size_t)(p3 & 0xFFFF) * 32 + lane];
        float f0 = pack_val(p0), f1 = pack_val(p1), f2 = pack_val(p2), f3 = pack_val(p3);
        unsigned long long v0 = pack_ff(f0, f0), v1 = pack_ff(f1, f1);
        unsigned long long v2 = pack_ff(f2, f2), v3 = pack_ff(f3, f3);
        fma2(aLo, h2_to_ff(h0.x), v0); fma2(aHi, h2_to_ff(h0.y), v0);
        fma2(bLo, h2_to_ff(h1.x), v1); fma2(bHi, h2_to_ff(h1.y), v1);
        fma2(aLo, h2_to_ff(h2.x), v2); fma2(aHi, h2_to_ff(h2.y), v2);
        fma2(bLo, h2_to_ff(h3.x), v3); fma2(bHi, h2_to_ff(h3.y), v3);
    }
    for (; i < deg; i++) {
        unsigned p = pk[i];
        uint2 h = H[(size_t)(p & 0xFFFF) * 32 + lane];
        float f = pack_val(p);
        unsigned long long v = pack_ff(f, f);
        fma2(aLo, h2_to_ff(h.x), v); fma2(aHi, h2_to_ff(h.y), v);
    }
}

__global__ void adj_relu_kernel(float* __restrict__ out) {
    int r    = (blockIdx.x * blockDim.x + threadIdx.x) >> 5;
    int lane = threadIdx.x & 31;
    if (r >= N_NODES) return;

    unsigned long long aLo = 0ULL, aHi = 0ULL;   // accumulator A (cols 01/23)
    unsigned long long bLo = 0ULL, bHi = 0ULL;   // accumulator B (cols 01/23)
    adj_accum<1>(r, lane, g_xw1h, aLo, aHi, bLo, bHi);
    adj_accum<2>(r, lane, g_xw2h, aLo, aHi, bLo, bHi);

    float2 A01 = unpack_ff(aLo), A23 = unpack_ff(aHi);
    float2 B01 = unpack_ff(bLo), B23 = unpack_ff(bHi);
    float4 acc;
    acc.x = fmaxf(A01.x + B01.x, 0.f);
    acc.y = fmaxf(A01.y + B01.y, 0.f);
    acc.z = fmaxf(A23.x + B23.x, 0.f);
    acc.w = fmaxf(A23.y + B23.y, 0.f);
    reinterpret_cast<float4*>(out + (size_t)r * OUT_DIM)[lane] = acc;
}

// ---------------------------------------------------------------------------
// Launch: identical structure to R15 (best known).
// ---------------------------------------------------------------------------
extern "C" void kernel_launch(void* const* d_in, const int* in_sizes, int n_in,
                              void* d_out, int out_size) {
    const int*   feat_row = (const int*)  d_in[0];
    const int*   feat_col = (const int*)  d_in[1];
    const float* feat_val = (const float*)d_in[2];
    const int*   a1_row   = (const int*)  d_in[3];
    const int*   a1_col   = (const int*)  d_in[4];
    const float* a1_val   = (const float*)d_in[5];
    const int*   a2_row   = (const int*)  d_in[6];
    const int*   a2_col   = (const int*)  d_in[7];
    const float* a2_val   = (const float*)d_in[8];
    const float* W1       = (const float*)d_in[9];
    const float* W2       = (const float*)d_in[10];
    float* out = (float*)d_out;

    const int nf = in_sizes[0];
    const int n1 = in_sizes[3];
    const int n2 = in_sizes[6];

    static cudaStream_t s1 = nullptr;
    static cudaEvent_t evPrep = nullptr, evAdj = nullptr;
    if (!s1) {
        cudaStreamCreateWithFlags(&s1, cudaStreamNonBlocking);
        cudaEventCreateWithFlags(&evPrep, cudaEventDisableTiming);
        cudaEventCreateWithFlags(&evAdj,  cudaEventDisableTiming);
    }

    // prep: zero counters + interleaved W conversion
    prep_kernel<<<256, 256>>>(W1, W2);
    cudaEventRecord(evPrep, 0);

    // side stream: adj scatter overlaps the feat pipeline
    cudaStreamWaitEvent(s1, evPrep, 0);
    scatter_adj_kernel<<<1024, 256, 0, s1>>>(a1_row, a1_col, a1_val,
                                             a2_row, a2_col, a2_val, n1, n2);
    cudaEventRecord(evAdj, s1);

    // main: feat scatter + feat SpMM
    scatter_feat_kernel<<<1024, 256>>>(feat_row, feat_col, feat_val, nf);
    const int node_blocks = (N_NODES + 7) / 8;
    feat_csr_kernel<<<node_blocks, 256>>>();

    // join
    cudaStreamWaitEvent(0, evAdj, 0);
    adj_relu_kernel<<<node_blocks, 256>>>(out);
}